// round 1
// baseline (speedup 1.0000x reference)
#include <cuda_runtime.h>
#include <cuda_bf16.h>

#define NNODES 100000
#define NEDGES 1600000
#define INDIM  1433
#define HID    50
#define OUTD   7
#define HP     64      // padded hidden stride (256B rows, cols 50..63 stay zero)

// ---------------- scratch (static device memory; zero-initialized at load) ----
__device__ int   g_counts[NNODES];
__device__ int   g_rowptr[NNODES + 1];
__device__ int   g_cursor[NNODES];
__device__ int   g_bsums[128];
__device__ int   g_src[NEDGES];
__device__ float g_dinv[NNODES];
__device__ float g_h1[NNODES * HP];   // layer-1 linear output (cols 50..63 == 0 forever)
__device__ float g_o1[NNODES * HP];   // layer-1 post-agg relu output
__device__ float g_z[NNODES * 8];     // layer-2 linear output (col 7 == 0 forever)

// ---------------- helpers ----------------
__device__ __forceinline__ unsigned cvt_tf32(float f) {
    unsigned u;
    asm("cvt.rna.tf32.f32 %0, %1;" : "=r"(u) : "f"(f));
    return u;
}

__device__ __forceinline__ void mma_tf32(float* c,
                                         unsigned a0, unsigned a1, unsigned a2, unsigned a3,
                                         unsigned b0, unsigned b1) {
    asm("mma.sync.aligned.m16n8k8.row.col.f32.tf32.tf32.f32 "
        "{%0,%1,%2,%3}, {%4,%5,%6,%7}, {%8,%9}, {%0,%1,%2,%3};"
        : "+f"(c[0]), "+f"(c[1]), "+f"(c[2]), "+f"(c[3])
        : "r"(a0), "r"(a1), "r"(a2), "r"(a3), "r"(b0), "r"(b1));
}

// ---------------- CSR build ----------------
__global__ void zero_counts_kernel() {
    int i = blockIdx.x * blockDim.x + threadIdx.x;
    if (i < NNODES) g_counts[i] = 0;
}

__global__ void count_kernel(const int* __restrict__ col) {
    int i = blockIdx.x * blockDim.x + threadIdx.x;
    if (i < NEDGES) atomicAdd(&g_counts[col[i]], 1);
}

__global__ void dinv_kernel() {
    int i = blockIdx.x * blockDim.x + threadIdx.x;
    if (i < NNODES) g_dinv[i] = rsqrtf((float)(g_counts[i] + 1));  // +1 self loop
}

__global__ void scan_local_kernel() {
    __shared__ int ws[32];
    int tid = threadIdx.x;
    int i = blockIdx.x * 1024 + tid;
    int v = (i < NNODES) ? g_counts[i] : 0;
    int x = v;
#pragma unroll
    for (int d = 1; d < 32; d <<= 1) {
        int y = __shfl_up_sync(0xffffffffu, x, d);
        if ((tid & 31) >= d) x += y;
    }
    if ((tid & 31) == 31) ws[tid >> 5] = x;
    __syncthreads();
    if (tid < 32) {
        int w = ws[tid];
#pragma unroll
        for (int d = 1; d < 32; d <<= 1) {
            int y = __shfl_up_sync(0xffffffffu, w, d);
            if (tid >= d) w += y;
        }
        ws[tid] = w;  // inclusive per-warp sums
    }
    __syncthreads();
    int woff = (tid >= 32) ? ws[(tid >> 5) - 1] : 0;
    int incl = x + woff;
    if (i < NNODES) g_rowptr[i] = incl - v;  // local exclusive scan
    if (tid == 1023) g_bsums[blockIdx.x] = incl;  // block total
}

__global__ void scan_bsums_kernel(int nblocks) {
    if (threadIdx.x == 0 && blockIdx.x == 0) {
        int running = 0;
        for (int b = 0; b < nblocks; b++) {
            int t = g_bsums[b];
            g_bsums[b] = running;
            running += t;
        }
    }
}

__global__ void scan_add_kernel() {
    int i = blockIdx.x * blockDim.x + threadIdx.x;
    if (i < NNODES) {
        int val = g_rowptr[i] + g_bsums[i >> 10];
        g_rowptr[i] = val;
        g_cursor[i] = val;
    }
    if (i == 0) g_rowptr[NNODES] = NEDGES;
}

__global__ void scatter_kernel(const int* __restrict__ row, const int* __restrict__ col) {
    int i = blockIdx.x * blockDim.x + threadIdx.x;
    if (i < NEDGES) {
        int c = col[i];
        int p = atomicAdd(&g_cursor[c], 1);
        g_src[p] = row[i];
    }
}

// ---------------- GEMM1: h1 = x @ W1 (tf32 tensor cores) ----------------
// Block: 256 threads = 8 warps. Block tile M=128 (warp=16 rows), N=56 (7 n-tiles), K chunks of 32.
#define KCHUNKS ((INDIM + 31) / 32)

__global__ __launch_bounds__(256) void gemm1_kernel(const float* __restrict__ x,
                                                    const float* __restrict__ w1) {
    __shared__ float As[128 * 36];  // ld=36: bank = 4*gid+tg (conflict-free)
    __shared__ float Bs[32 * 72];   // ld=72: bank = 8*tg+gid (conflict-free)
    int t = threadIdx.x;
    int lane = t & 31, warp = t >> 5;
    int gid = lane >> 2, tg = lane & 3;
    int mbase = blockIdx.x * 128;

    float acc[7][4];
#pragma unroll
    for (int i = 0; i < 7; i++)
#pragma unroll
        for (int j = 0; j < 4; j++) acc[i][j] = 0.f;

    for (int kc = 0; kc < KCHUNKS; kc++) {
        int kb = kc * 32;
        // load A tile 128x32
#pragma unroll
        for (int p = 0; p < 4; p++) {
            int r = p * 32 + (t >> 3);
            int row = mbase + r;
#pragma unroll
            for (int i = 0; i < 4; i++) {
                int c = (t & 7) + i * 8;
                int k = kb + c;
                float v = (row < NNODES && k < INDIM) ? __ldg(&x[row * INDIM + k]) : 0.f;
                As[r * 36 + c] = __uint_as_float(cvt_tf32(v));
            }
        }
        // load B tile 32x56
        for (int idx = t; idx < 32 * 56; idx += 256) {
            int kk = idx / 56, n = idx % 56;
            int k = kb + kk;
            float v = (k < INDIM && n < HID) ? __ldg(&w1[k * HID + n]) : 0.f;
            Bs[kk * 72 + n] = __uint_as_float(cvt_tf32(v));
        }
        __syncthreads();

        int ar = warp * 16 + gid;
#pragma unroll
        for (int k8 = 0; k8 < 4; k8++) {
            int kk = k8 * 8;
            unsigned a0 = __float_as_uint(As[(ar)     * 36 + kk + tg]);
            unsigned a1 = __float_as_uint(As[(ar + 8) * 36 + kk + tg]);
            unsigned a2 = __float_as_uint(As[(ar)     * 36 + kk + tg + 4]);
            unsigned a3 = __float_as_uint(As[(ar + 8) * 36 + kk + tg + 4]);
#pragma unroll
            for (int nt = 0; nt < 7; nt++) {
                unsigned b0 = __float_as_uint(Bs[(kk + tg)     * 72 + nt * 8 + gid]);
                unsigned b1 = __float_as_uint(Bs[(kk + tg + 4) * 72 + nt * 8 + gid]);
                mma_tf32(acc[nt], a0, a1, a2, a3, b0, b1);
            }
        }
        __syncthreads();
    }

    // epilogue: C frag (16x8): c0 at (gid, 2*tg), c1 +1 col, c2/c3 at row+8
    int rbase = mbase + warp * 16;
#pragma unroll
    for (int nt = 0; nt < 7; nt++) {
#pragma unroll
        for (int half = 0; half < 2; half++) {
            int r = rbase + gid + half * 8;
            int ccol = nt * 8 + tg * 2;
            if (r < NNODES && ccol < HID) {
                g_h1[r * HP + ccol]     = acc[nt][half * 2 + 0];
                g_h1[r * HP + ccol + 1] = acc[nt][half * 2 + 1];
            }
        }
    }
}

// ---------------- Aggregation 1 (CSR gather, +self loop, +b1, relu) ----------------
// Block 256 = 4 nodes x 64 lanes. Lanes f>=50 read zero pad columns (harmless, uniform).
__global__ __launch_bounds__(256) void agg1_kernel(const float* __restrict__ b1) {
    int t = threadIdx.x;
    int f = t & 63;
    int v = blockIdx.x * 4 + (t >> 6);
    if (v >= NNODES) return;
    int s0 = __ldg(&g_rowptr[v]);
    int s1 = __ldg(&g_rowptr[v + 1]);
    float dv = g_dinv[v];
    float acc = dv * __ldg(&g_h1[v * HP + f]);  // self loop: dinv[v]^2 * h[v] (dv applied below)
    int j = s0;
    for (; j + 1 < s1; j += 2) {
        int sa = __ldg(&g_src[j]);
        int sb = __ldg(&g_src[j + 1]);
        float wa = __ldg(&g_dinv[sa]);
        float wb = __ldg(&g_dinv[sb]);
        float ha = __ldg(&g_h1[sa * HP + f]);
        float hb = __ldg(&g_h1[sb * HP + f]);
        acc = fmaf(wa, ha, acc);
        acc = fmaf(wb, hb, acc);
    }
    if (j < s1) {
        int sa = __ldg(&g_src[j]);
        acc = fmaf(__ldg(&g_dinv[sa]), __ldg(&g_h1[sa * HP + f]), acc);
    }
    if (f < HID) {
        float r = dv * acc + __ldg(&b1[f]);
        g_o1[v * HP + f] = fmaxf(r, 0.f);
    }
}

// ---------------- Layer 2 linear: z = o1 @ W2 ----------------
__global__ __launch_bounds__(256) void lin2_kernel(const float* __restrict__ w2) {
    __shared__ float tile[32 * 65];
    __shared__ float w2s[HID * OUTD];
    int t = threadIdx.x;
    int base = blockIdx.x * 32;
    for (int i = t; i < HID * OUTD; i += 256) w2s[i] = w2[i];
    for (int i = t; i < 32 * 64; i += 256) {
        int v = i >> 6, f = i & 63;
        tile[v * 65 + f] = g_o1[(base + v) * HP + f];
    }
    __syncthreads();
    if (t < 32 * OUTD) {
        int v = t / OUTD, jj = t % OUTD;
        float s = 0.f;
#pragma unroll
        for (int f = 0; f < HID; f++) s = fmaf(tile[v * 65 + f], w2s[f * OUTD + jj], s);
        g_z[(base + v) * 8 + jj] = s;
    }
}

// ---------------- Aggregation 2 (+b2, sigmoid) ----------------
// Block 256 = 32 nodes x 8 lanes. Lane jj==7 reads z pad (zero), discarded.
__global__ __launch_bounds__(256) void agg2_kernel(const float* __restrict__ b2,
                                                   float* __restrict__ out) {
    int t = threadIdx.x;
    int jj = t & 7;
    int v = blockIdx.x * 32 + (t >> 3);
    if (v >= NNODES) return;
    int s0 = __ldg(&g_rowptr[v]);
    int s1 = __ldg(&g_rowptr[v + 1]);
    float dv = g_dinv[v];
    float acc = dv * __ldg(&g_z[v * 8 + jj]);
    int j = s0;
    for (; j + 1 < s1; j += 2) {
        int sa = __ldg(&g_src[j]);
        int sb = __ldg(&g_src[j + 1]);
        acc = fmaf(__ldg(&g_dinv[sa]), __ldg(&g_z[sa * 8 + jj]), acc);
        acc = fmaf(__ldg(&g_dinv[sb]), __ldg(&g_z[sb * 8 + jj]), acc);
    }
    if (j < s1) {
        int sa = __ldg(&g_src[j]);
        acc = fmaf(__ldg(&g_dinv[sa]), __ldg(&g_z[sa * 8 + jj]), acc);
    }
    if (jj < OUTD) {
        float zz = dv * acc + __ldg(&b2[jj]);
        out[v * OUTD + jj] = 1.f / (1.f + __expf(-zz));
    }
}

// ---------------- launch ----------------
extern "C" void kernel_launch(void* const* d_in, const int* in_sizes, int n_in,
                              void* d_out, int out_size) {
    const float* x  = (const float*)d_in[0];
    const int*   ei = (const int*)d_in[1];
    const float* w1 = (const float*)d_in[2];
    const float* b1 = (const float*)d_in[3];
    const float* w2 = (const float*)d_in[4];
    const float* b2 = (const float*)d_in[5];
    float* out = (float*)d_out;

    const int* row = ei;            // edge_index[0] = src
    const int* col = ei + NEDGES;   // edge_index[1] = dst

    // CSR build (by destination) + degree norm
    zero_counts_kernel<<<391, 256>>>();
    count_kernel<<<6250, 256>>>(col);
    dinv_kernel<<<391, 256>>>();
    scan_local_kernel<<<98, 1024>>>();
    scan_bsums_kernel<<<1, 32>>>(98);
    scan_add_kernel<<<391, 256>>>();
    scatter_kernel<<<6250, 256>>>(row, col);

    // GCN layer 1
    gemm1_kernel<<<(NNODES + 127) / 128, 256>>>(x, w1);
    agg1_kernel<<<NNODES / 4, 256>>>(b1);

    // GCN layer 2
    lin2_kernel<<<NNODES / 32, 256>>>(w2);
    agg2_kernel<<<NNODES / 32, 256>>>(b2, out);
}

// round 2
// speedup vs baseline: 2.6959x; 2.6959x over previous
#include <cuda_runtime.h>
#include <cuda_bf16.h>

#define NNODES 100000
#define NEDGES 1600000
#define INDIM  1433
#define HID    50
#define OUTD   7
#define HP     64      // padded hidden stride (256B rows; cols 50..63 stay zero forever)
#define KCHUNKS 45     // ceil(1433/32)

// ---------------- scratch (static device memory; zero-initialized at load) ----
__device__ int   g_counts[NNODES];        // zeroed by scan_add for next replay
__device__ int   g_rowptr[NNODES + 1];
__device__ int   g_cursor[NNODES];
__device__ int   g_bsums[128];
__device__ int2  g_edge[NEDGES];          // {src, bits(dinv[src])}
__device__ float g_dinv[NNODES];
__device__ float g_h1[NNODES * HP];       // layer-1 linear out (pad cols stay 0)
__device__ float g_z[NNODES * 8];         // layer-2 linear out (col 7 stays 0)
__device__ float g_w1p[KCHUNKS * 2048];   // W1 pre-padded: [45][32][64]

// ---------------- mma helper ----------------
__device__ __forceinline__ void mma_tf32(float* c,
                                         unsigned a0, unsigned a1, unsigned a2, unsigned a3,
                                         unsigned b0, unsigned b1) {
    asm("mma.sync.aligned.m16n8k8.row.col.f32.tf32.tf32.f32 "
        "{%0,%1,%2,%3}, {%4,%5,%6,%7}, {%8,%9}, {%0,%1,%2,%3};"
        : "+f"(c[0]), "+f"(c[1]), "+f"(c[2]), "+f"(c[3])
        : "r"(a0), "r"(a1), "r"(a2), "r"(a3), "r"(b0), "r"(b1));
}

// ---------------- W1 pre-pad: [45][32][64], zero padding ----------------
__global__ void w1pad_kernel(const float* __restrict__ w1) {
    int i = blockIdx.x * 256 + threadIdx.x;
    if (i < KCHUNKS * 2048) {
        int kc = i >> 11, rem = i & 2047;
        int kk = rem >> 6, n = rem & 63;
        int k = kc * 32 + kk;
        g_w1p[i] = (k < INDIM && n < HID) ? __ldg(&w1[k * HID + n]) : 0.f;
    }
}

// ---------------- CSR build ----------------
__global__ void count_kernel(const int* __restrict__ col) {
    int i = blockIdx.x * blockDim.x + threadIdx.x;
    if (i < NEDGES) atomicAdd(&g_counts[__ldg(&col[i])], 1);
}

__global__ void dinv_kernel() {
    int i = blockIdx.x * blockDim.x + threadIdx.x;
    if (i < NNODES) g_dinv[i] = rsqrtf((float)(g_counts[i] + 1));  // +1 self loop
}

__global__ void scan_local_kernel() {
    __shared__ int ws[32];
    int tid = threadIdx.x;
    int i = blockIdx.x * 1024 + tid;
    int v = (i < NNODES) ? g_counts[i] : 0;
    int x = v;
#pragma unroll
    for (int d = 1; d < 32; d <<= 1) {
        int y = __shfl_up_sync(0xffffffffu, x, d);
        if ((tid & 31) >= d) x += y;
    }
    if ((tid & 31) == 31) ws[tid >> 5] = x;
    __syncthreads();
    if (tid < 32) {
        int w = ws[tid];
#pragma unroll
        for (int d = 1; d < 32; d <<= 1) {
            int y = __shfl_up_sync(0xffffffffu, w, d);
            if (tid >= d) w += y;
        }
        ws[tid] = w;
    }
    __syncthreads();
    int woff = (tid >= 32) ? ws[(tid >> 5) - 1] : 0;
    int incl = x + woff;
    if (i < NNODES) g_rowptr[i] = incl - v;       // local exclusive
    if (tid == 1023) g_bsums[blockIdx.x] = incl;  // block total
}

// parallel exclusive scan of 98 block sums (1 block, 128 threads)
__global__ void scan_bsums_kernel() {
    __shared__ int ws[4];
    int tid = threadIdx.x;
    int v = (tid < 98) ? g_bsums[tid] : 0;
    int x = v;
#pragma unroll
    for (int d = 1; d < 32; d <<= 1) {
        int y = __shfl_up_sync(0xffffffffu, x, d);
        if ((tid & 31) >= d) x += y;
    }
    if ((tid & 31) == 31) ws[tid >> 5] = x;
    __syncthreads();
    if (tid < 4) {
        int wv = ws[tid];
#pragma unroll
        for (int d = 1; d < 4; d <<= 1) {
            int y = __shfl_up_sync(0x0000000fu, wv, d);
            if (tid >= d) wv += y;
        }
        ws[tid] = wv;
    }
    __syncthreads();
    int off = (tid >= 32) ? ws[(tid >> 5) - 1] : 0;
    if (tid < 98) g_bsums[tid] = x + off - v;
}

__global__ void scan_add_kernel() {
    int i = blockIdx.x * blockDim.x + threadIdx.x;
    if (i < NNODES) {
        int val = g_rowptr[i] + g_bsums[i >> 10];
        g_rowptr[i] = val;
        g_cursor[i] = val;
        g_counts[i] = 0;  // reset for next graph replay
    }
    if (i == 0) g_rowptr[NNODES] = NEDGES;
}

__global__ void scatter_kernel(const int* __restrict__ row, const int* __restrict__ col) {
    int i = blockIdx.x * blockDim.x + threadIdx.x;
    if (i < NEDGES) {
        int c = __ldg(&col[i]);
        int r = __ldg(&row[i]);
        int p = atomicAdd(&g_cursor[c], 1);
        g_edge[p] = make_int2(r, __float_as_int(__ldg(&g_dinv[r])));
    }
}

// ---------------- GEMM1: h1 = x @ W1 (tf32 HMMA, pipelined) ----------------
// 128 threads = 4 warps; block tile M=128 (warp 32 rows), N=56, K chunk 32.
__global__ __launch_bounds__(128, 3) void gemm1_kernel(const float* __restrict__ x,
                                                       int mbase0) {
    __shared__ float As[128 * 36];  // LDS frag bank = 4*gid+tg : conflict-free
    __shared__ float Bs[32 * 72];   // LDS frag bank = 8*tg+gid : conflict-free
    int t = threadIdx.x, lane = t & 31, w = t >> 5;
    int gid = lane >> 2, tg = lane & 3;
    int mbase = mbase0 + blockIdx.x * 128;
    int row0 = mbase + w * 32;

    float acc[14][4];
#pragma unroll
    for (int i = 0; i < 14; i++)
#pragma unroll
        for (int j = 0; j < 4; j++) acc[i][j] = 0.f;

    float aReg[32];
    float4 bReg[4];
    const float4* w1p4 = (const float4*)g_w1p;

    // prologue: stage chunk 0
#pragma unroll
    for (int i = 0; i < 32; i++) {
        int r = row0 + i;
        aReg[i] = (r < NNODES) ? __ldg(&x[(size_t)r * INDIM + lane]) : 0.f;
    }
#pragma unroll
    for (int i = 0; i < 4; i++) bReg[i] = __ldg(&w1p4[t + i * 128]);

    for (int kc = 0; kc < KCHUNKS; kc++) {
        // commit staged tile to smem
#pragma unroll
        for (int i = 0; i < 32; i++) As[(w * 32 + i) * 36 + lane] = aReg[i];
#pragma unroll
        for (int i = 0; i < 4; i++) {
            int idx = (t + i * 128) * 4;
            int kk = idx >> 6, n = idx & 63;
            *(float4*)&Bs[kk * 72 + n] = bReg[i];
        }
        __syncthreads();
        // prefetch next chunk into regs (overlaps MMA below)
        if (kc < KCHUNKS - 1) {
            int kb = (kc + 1) * 32;
            bool kok = (kb + lane) < INDIM;
#pragma unroll
            for (int i = 0; i < 32; i++) {
                int r = row0 + i;
                aReg[i] = (r < NNODES && kok) ? __ldg(&x[(size_t)r * INDIM + kb + lane]) : 0.f;
            }
#pragma unroll
            for (int i = 0; i < 4; i++) bReg[i] = __ldg(&w1p4[(kc + 1) * 512 + t + i * 128]);
        }
        // MMA over current tile
#pragma unroll
        for (int k8 = 0; k8 < 4; k8++) {
            int kk = k8 * 8;
            unsigned b0[7], b1[7];
#pragma unroll
            for (int nt = 0; nt < 7; nt++) {
                b0[nt] = __float_as_uint(Bs[(kk + tg) * 72 + nt * 8 + gid]);
                b1[nt] = __float_as_uint(Bs[(kk + tg + 4) * 72 + nt * 8 + gid]);
            }
#pragma unroll
            for (int mt = 0; mt < 2; mt++) {
                int ar = w * 32 + mt * 16 + gid;
                unsigned a0 = __float_as_uint(As[ar * 36 + kk + tg]);
                unsigned a1 = __float_as_uint(As[(ar + 8) * 36 + kk + tg]);
                unsigned a2 = __float_as_uint(As[ar * 36 + kk + tg + 4]);
                unsigned a3 = __float_as_uint(As[(ar + 8) * 36 + kk + tg + 4]);
#pragma unroll
                for (int nt = 0; nt < 7; nt++)
                    mma_tf32(acc[mt * 7 + nt], a0, a1, a2, a3, b0[nt], b1[nt]);
            }
        }
        __syncthreads();
    }

    // epilogue
#pragma unroll
    for (int mt = 0; mt < 2; mt++) {
#pragma unroll
        for (int nt = 0; nt < 7; nt++) {
            int c0 = nt * 8 + tg * 2;
            if (c0 < HID) {
#pragma unroll
                for (int h = 0; h < 2; h++) {
                    int r = mbase + w * 32 + mt * 16 + gid + h * 8;
                    if (r < NNODES) {
                        float2 v = make_float2(acc[mt * 7 + nt][h * 2], acc[mt * 7 + nt][h * 2 + 1]);
                        *(float2*)&g_h1[(size_t)r * HP + c0] = v;
                    }
                }
            }
        }
    }
}

// ---------------- Aggregation 1 + fused lin2 ----------------
// 1 node per warp (32 lanes x float2 = 64 cols). z = relu(agg)@W2 via shuffles.
__global__ __launch_bounds__(256) void agg1_kernel(const float* __restrict__ b1,
                                                   const float* __restrict__ w2) {
    __shared__ float w2s[HID * OUTD];
    int t = threadIdx.x, lane = t & 31, w = t >> 5;
    for (int i = t; i < HID * OUTD; i += 256) w2s[i] = __ldg(&w2[i]);
    __syncthreads();
    int v = blockIdx.x * 8 + w;
    if (v >= NNODES) return;
    int s0 = __ldg(&g_rowptr[v]);
    int s1 = __ldg(&g_rowptr[v + 1]);
    float dv = __ldg(&g_dinv[v]);
    const float2* hb = (const float2*)g_h1;
    float2 self = __ldg(&hb[(size_t)v * 32 + lane]);
    float ax = dv * self.x, ay = dv * self.y;
    int j = s0;
    for (; j + 3 < s1; j += 4) {
        int2 e0 = __ldg(&g_edge[j]);
        int2 e1 = __ldg(&g_edge[j + 1]);
        int2 e2 = __ldg(&g_edge[j + 2]);
        int2 e3 = __ldg(&g_edge[j + 3]);
        float2 h0 = __ldg(&hb[(size_t)e0.x * 32 + lane]);
        float2 h1v = __ldg(&hb[(size_t)e1.x * 32 + lane]);
        float2 h2 = __ldg(&hb[(size_t)e2.x * 32 + lane]);
        float2 h3 = __ldg(&hb[(size_t)e3.x * 32 + lane]);
        float w0 = __int_as_float(e0.y), w1v = __int_as_float(e1.y);
        float w2v = __int_as_float(e2.y), w3 = __int_as_float(e3.y);
        ax = fmaf(w0, h0.x, ax);  ay = fmaf(w0, h0.y, ay);
        ax = fmaf(w1v, h1v.x, ax); ay = fmaf(w1v, h1v.y, ay);
        ax = fmaf(w2v, h2.x, ax); ay = fmaf(w2v, h2.y, ay);
        ax = fmaf(w3, h3.x, ax);  ay = fmaf(w3, h3.y, ay);
    }
    for (; j < s1; j++) {
        int2 e = __ldg(&g_edge[j]);
        float2 h0 = __ldg(&hb[(size_t)e.x * 32 + lane]);
        float we = __int_as_float(e.y);
        ax = fmaf(we, h0.x, ax);
        ay = fmaf(we, h0.y, ay);
    }
    int f0 = 2 * lane, f1 = 2 * lane + 1;
    float o1x = (f0 < HID) ? fmaxf(fmaf(dv, ax, __ldg(&b1[f0])), 0.f) : 0.f;
    float o1y = (f1 < HID) ? fmaxf(fmaf(dv, ay, __ldg(&b1[f1])), 0.f) : 0.f;
    float z[7];
#pragma unroll
    for (int jo = 0; jo < 7; jo++) {
        float p = 0.f;
        if (f0 < HID) p = o1x * w2s[f0 * OUTD + jo];
        if (f1 < HID) p = fmaf(o1y, w2s[f1 * OUTD + jo], p);
#pragma unroll
        for (int d = 16; d >= 1; d >>= 1) p += __shfl_xor_sync(0xffffffffu, p, d);
        z[jo] = p;
    }
    if (lane == 0) {
#pragma unroll
        for (int jo = 0; jo < 7; jo++) g_z[(size_t)v * 8 + jo] = z[jo];
    }
}

// ---------------- Aggregation 2 (+b2, sigmoid) ----------------
__global__ __launch_bounds__(256) void agg2_kernel(const float* __restrict__ b2,
                                                   float* __restrict__ out) {
    int t = threadIdx.x;
    int jj = t & 7;
    int v = blockIdx.x * 32 + (t >> 3);
    int s0 = __ldg(&g_rowptr[v]);
    int s1 = __ldg(&g_rowptr[v + 1]);
    float dv = __ldg(&g_dinv[v]);
    float acc = dv * __ldg(&g_z[(size_t)v * 8 + jj]);
    int j = s0;
    for (; j + 3 < s1; j += 4) {
        int2 e0 = __ldg(&g_edge[j]);
        int2 e1 = __ldg(&g_edge[j + 1]);
        int2 e2 = __ldg(&g_edge[j + 2]);
        int2 e3 = __ldg(&g_edge[j + 3]);
        acc = fmaf(__int_as_float(e0.y), __ldg(&g_z[(size_t)e0.x * 8 + jj]), acc);
        acc = fmaf(__int_as_float(e1.y), __ldg(&g_z[(size_t)e1.x * 8 + jj]), acc);
        acc = fmaf(__int_as_float(e2.y), __ldg(&g_z[(size_t)e2.x * 8 + jj]), acc);
        acc = fmaf(__int_as_float(e3.y), __ldg(&g_z[(size_t)e3.x * 8 + jj]), acc);
    }
    for (; j < s1; j++) {
        int2 e = __ldg(&g_edge[j]);
        acc = fmaf(__int_as_float(e.y), __ldg(&g_z[(size_t)e.x * 8 + jj]), acc);
    }
    if (jj < OUTD) {
        float zz = fmaf(dv, acc, __ldg(&b2[jj]));
        out[v * OUTD + jj] = 1.f / (1.f + __expf(-zz));
    }
}

// ---------------- launch ----------------
extern "C" void kernel_launch(void* const* d_in, const int* in_sizes, int n_in,
                              void* d_out, int out_size) {
    const float* x  = (const float*)d_in[0];
    const int*   ei = (const int*)d_in[1];
    const float* w1 = (const float*)d_in[2];
    const float* b1 = (const float*)d_in[3];
    const float* w2 = (const float*)d_in[4];
    const float* b2 = (const float*)d_in[5];
    float* out = (float*)d_out;

    const int* row = ei;            // edge_index[0] = src
    const int* col = ei + NEDGES;   // edge_index[1] = dst

    w1pad_kernel<<<360, 256>>>(w1);                 // 1
    count_kernel<<<6250, 256>>>(col);               // 2 (counts were zeroed last replay)
    dinv_kernel<<<391, 256>>>();                    // 3
    gemm1_kernel<<<391, 128>>>(x, 0);               // 4  <- profile window
    gemm1_kernel<<<391, 128>>>(x, 391 * 128);       // 5
    scan_local_kernel<<<98, 1024>>>();              // 6
    scan_bsums_kernel<<<1, 128>>>();                // 7
    scan_add_kernel<<<391, 256>>>();                // 8 (also zeroes counts)
    scatter_kernel<<<6250, 256>>>(row, col);        // 9
    agg1_kernel<<<12500, 256>>>(b1, w2);            // 10 (fused lin2)
    agg2_kernel<<<3125, 256>>>(b2, out);            // 11
}